// round 12
// baseline (speedup 1.0000x reference)
#include <cuda_runtime.h>
#include <cstdint>

#define KC 512
#define DC 256
#define BC 32
#define TC 4096
#define BT 128
#define EPS 2.5e-4f

// smem layout (bytes)
#define OFF_Z1P 0                      // [64 d4][128 t] int  (32KB)
#define OFF_Z2P 32768                  // [64 d4][128 t] int  (32KB)
#define OFF_WB0 65536                  // buf0: w1 32KB + w2 32KB
#define OFF_WB1 131072                 // buf1
#define OFF_WQ  196608                 // float[512]
#define OFF_ZQS 198656                 // float[128]
#define OFF_ZFL 199168                 // char[128] outlier flags
#define SMEM_BYTES 199424
// ztmp (fp32 staging, 128x132x4 = 67.6KB) aliases OFF_WB0.. during prologue

// prepped codebook: packed int8 quads, layout [d4][k] int
__device__ int g_w1p[64 * KC];
__device__ int g_w2p[64 * KC];
__device__ float g_wq[KC];
__device__ int g_cnt;
__device__ int g_list[BC * TC];

__device__ __forceinline__ uint32_t smem_u32(const void* p) {
    uint32_t a;
    asm("{ .reg .u64 t; cvta.to.shared.u64 t, %1; cvt.u32.u64 %0, t; }" : "=r"(a) : "l"(p));
    return a;
}
__device__ __forceinline__ void cp16(uint32_t dst, const void* src) {
    asm volatile("cp.async.cg.shared.global [%0], [%1], 16;" :: "r"(dst), "l"(src));
}
// signed 4x int8 dot-product accumulate: c += dot(a.s8x4, b.s8x4)
__device__ __forceinline__ int dp4a_s(int a, int b, int c) {
    int r;
    asm("dp4a.s32.s32 %0, %1, %2, %3;" : "=r"(r) : "r"(a), "r"(b), "r"(c));
    return r;
}

// ---- prep: int8 split of w (w1 = rn(w*2^15), w2 = rn((w-w1/2^15)*2^22)); exact ||w||^2 ----
__global__ void prep_kernel(const float* __restrict__ w) {
    int k = blockIdx.x, d = threadIdx.x;
    if (k == 0 && d == 0) g_cnt = 0;
    float wv = w[k * DC + d];
    int i1 = __float2int_rn(wv * 32768.0f);                       // |w|<=1/512 -> |i1|<=64
    float r = wv - (float)i1 * 3.0517578125e-5f;                  // residual, |r| <= 2^-16
    int i2 = __float2int_rn(r * 4194304.0f);                      // |i2| <= 64
    ((signed char*)g_w1p)[(d >> 2) * 2048 + (k << 2) + (d & 3)] = (signed char)i1;
    ((signed char*)g_w2p)[(d >> 2) * 2048 + (k << 2) + (d & 3)] = (signed char)i2;
    if (d == 0) {
        const float4* wr = (const float4*)(w + (size_t)k * DC);
        float s = 0.f;
        #pragma unroll
        for (int c = 0; c < DC / 4; ++c) {
            float4 v = wr[c];
            s += v.x * v.x + v.y * v.y + v.z * v.z + v.w * v.w;
        }
        g_wq[k] = s;
    }
}

// ---- main: dp4a triple-product distances + exact-rounded top-2 argmin + EPS flag ----
__global__ __launch_bounds__(256, 1)
void vq_dp4a_kernel(const float* __restrict__ z, float* __restrict__ out)
{
    extern __shared__ char smem[];
    const uint32_t sb = smem_u32(smem);
    int* z1p = (int*)(smem + OFF_Z1P);
    int* z2p = (int*)(smem + OFF_Z2P);
    float* ztmp = (float*)(smem + OFF_WB0);       // [128 d][132] fp32, dead after prologue
    float* wqs  = (float*)(smem + OFF_WQ);
    float* zqs  = (float*)(smem + OFF_ZQS);
    char*  zfl  = (char*)(smem + OFF_ZFL);

    const int tid = threadIdx.x, lane = tid & 31;
    const int b = blockIdx.y, t0 = blockIdx.x * BT;
    const float4* zg4 = (const float4*)(z + (size_t)b * DC * TC + t0);

    if (tid < BT) zfl[tid] = 0;

    // ---- Prologue: stage fp32 -> exact-serial z_sq -> int8 split quant ----
    float zq = 0.f, amax = 0.f;
    for (int h = 0; h < 2; ++h) {
        if (h) __syncthreads();
        #pragma unroll 4
        for (int i = 0; i < 16; ++i) {
            int f = tid + 256 * i, d = f >> 5, c = f & 31;
            float4 v = zg4[(size_t)(h * 128 + d) * (TC / 4) + c];
            *(float4*)(ztmp + d * 132 + c * 4) = v;
        }
        __syncthreads();
        if (tid < BT) {
            #pragma unroll 8
            for (int d = 0; d < 128; ++d) {        // serial d-order: validated R5 semantics
                float v = ztmp[d * 132 + tid];
                zq = __fadd_rn(zq, __fmul_rn(v, v));
            }
        }
        {
            int t = tid & 127, dbase = (tid >> 7) * 64;
            #pragma unroll 4
            for (int g = 0; g < 16; ++g) {
                int d0 = dbase + g * 4;
                unsigned int p1 = 0, p2 = 0;
                #pragma unroll
                for (int u = 0; u < 4; ++u) {
                    float v = ztmp[(d0 + u) * 132 + t];
                    amax = fmaxf(amax, fabsf(v));
                    int i1 = __float2int_rn(v * 16.0f);
                    float r = v - (float)i1 * 0.0625f;
                    int i2 = __float2int_rn(r * 2048.0f);
                    p1 |= (unsigned int)(i1 & 255) << (8 * u);
                    p2 |= (unsigned int)(i2 & 255) << (8 * u);
                }
                int d4g = h * 32 + (dbase >> 2) + g;
                z1p[d4g * 128 + t] = (int)p1;
                z2p[d4g * 128 + t] = (int)p2;
            }
        }
    }
    if (tid < BT) zqs[tid] = zq;
    if (amax > 7.8f) zfl[tid & 127] = 1;          // quantizer-range insurance
    #pragma unroll
    for (int i = 0; i < 2; ++i) wqs[tid + 256 * i] = g_wq[tid + 256 * i];
    __syncthreads();                               // ztmp dead; buffers usable

    // ---- prefetch chunk 0 (128 codes: w1 + w2, 64KB) into buf0 ----
    {
        for (int f = tid; f < 4096; f += 256) {
            int seg = f >> 5, g = f & 31;
            int comp = seg >> 6, d4 = seg & 63;
            const char* src = (const char*)(comp ? g_w2p : g_w1p) + d4 * 2048 + g * 16;
            cp16(sb + OFF_WB0 + comp * 32768 + d4 * 512 + g * 16, src);
        }
        asm volatile("cp.async.commit_group;" ::: "memory");
        asm volatile("cp.async.wait_group 0;" ::: "memory");
    }
    __syncthreads();

    const int tx = tid & 15, ty = tid >> 4;        // thread tile: 8t x 8k (k strided by 16)
    unsigned long long t1[8];
    float f2[8];
    #pragma unroll
    for (int i = 0; i < 8; ++i) { t1[i] = ~0ull; f2[i] = 3.402823466e38f; }

    for (int ch = 0; ch < 4; ++ch) {
        const int cur = ch & 1;
        if (ch < 3) {                              // prefetch next chunk into other buffer
            uint32_t dbase = sb + ((cur ^ 1) ? OFF_WB1 : OFF_WB0);
            for (int f = tid; f < 4096; f += 256) {
                int seg = f >> 5, g = f & 31;
                int comp = seg >> 6, d4 = seg & 63;
                const char* src = (const char*)(comp ? g_w2p : g_w1p)
                                  + d4 * 2048 + (ch + 1) * 512 + g * 16;
                cp16(dbase + comp * 32768 + d4 * 512 + g * 16, src);
            }
            asm volatile("cp.async.commit_group;" ::: "memory");
        }

        const int* w1p = (const int*)(smem + (cur ? OFF_WB1 : OFF_WB0));
        const int* w2p = w1p + 8192;

        int s1[8][8], s23[8][8];
        #pragma unroll
        for (int i = 0; i < 8; ++i)
            #pragma unroll
            for (int j = 0; j < 8; ++j) { s1[i][j] = 0; s23[i][j] = 0; }

        #pragma unroll 4
        for (int d4 = 0; d4 < 64; ++d4) {
            int z1r[8], z2r[8], w1r[8], w2r[8];
            #pragma unroll
            for (int i = 0; i < 4; ++i) {          // int2 loads over t pairs
                int2 a = *(const int2*)&z1p[d4 * 128 + ty * 8 + 2 * i];
                int2 c = *(const int2*)&z2p[d4 * 128 + ty * 8 + 2 * i];
                z1r[2 * i] = a.x; z1r[2 * i + 1] = a.y;
                z2r[2 * i] = c.x; z2r[2 * i + 1] = c.y;
            }
            #pragma unroll
            for (int j = 0; j < 8; ++j) {          // k = j*16 + tx : conflict-free
                w1r[j] = w1p[d4 * 128 + j * 16 + tx];
                w2r[j] = w2p[d4 * 128 + j * 16 + tx];
            }
            #pragma unroll
            for (int i = 0; i < 8; ++i)
                #pragma unroll
                for (int j = 0; j < 8; ++j) {
                    s1[i][j]  = dp4a_s(z1r[i], w1r[j], s1[i][j]);
                    s23[i][j] = dp4a_s(z1r[i], w2r[j], s23[i][j]);
                    s23[i][j] = dp4a_s(z2r[i], w1r[j], s23[i][j]);
                }
        }

        // ---- epilogue: exact reference rounding; top1(u64) + second-best value ----
        #pragma unroll
        for (int i = 0; i < 8; ++i) {
            float zqv = zqs[ty * 8 + i];
            #pragma unroll
            for (int j = 0; j < 8; ++j) {
                int k = ch * 128 + j * 16 + tx;
                float cross = (float)s1[i][j] * 1.9073486328125e-6f
                            + (float)s23[i][j] * 1.4901161193847656e-8f;
                float c2 = __fmul_rn(2.0f, cross);
                float t2 = __fsub_rn(zqv, c2);
                float s  = __fadd_rn(t2, wqs[k]);
                unsigned long long cand =
                    (((unsigned long long)__float_as_uint(s)) << 32) | (uint32_t)k;
                if (cand < t1[i]) {
                    f2[i] = __uint_as_float((uint32_t)(t1[i] >> 32));
                    t1[i] = cand;
                } else {
                    f2[i] = fminf(f2[i], s);
                }
            }
        }

        if (ch < 3) {
            asm volatile("cp.async.wait_group 0;" ::: "memory");
            __syncthreads();
        }
    }

    // ---- reduce across the 16 tx threads (xor 1,2,4,8 stays in 16-lane group) ----
    #pragma unroll
    for (int i = 0; i < 8; ++i) {
        unsigned long long v1 = t1[i];
        float vf2 = f2[i];
        #pragma unroll
        for (int off = 1; off <= 8; off <<= 1) {
            unsigned long long o1 = __shfl_xor_sync(0xffffffffu, v1, off);
            float of2 = __shfl_xor_sync(0xffffffffu, vf2, off);
            float loser;
            if (o1 < v1) { loser = __uint_as_float((uint32_t)(v1 >> 32)); v1 = o1; }
            else         { loser = __uint_as_float((uint32_t)(o1 >> 32)); }
            vf2 = fminf(fminf(vf2, of2), loser);
        }
        if ((lane & 15) == 0) {
            int row = ty * 8 + i;
            int qid = b * TC + t0 + row;
            out[qid] = (float)(unsigned int)(v1 & 0xFFFFFFFFull);
            float f1v = __uint_as_float((uint32_t)(v1 >> 32));
            if (__fsub_rn(vf2, f1v) < EPS || zfl[row]) {
                int idx = atomicAdd(&g_cnt, 1);
                g_list[idx] = qid;
            }
        }
    }
}

// ---- kernel B: exact R5-semantics re-resolve for flagged queries (validated) ----
__global__ __launch_bounds__(256, 1)
void fix_kernel(const float* __restrict__ z, const float* __restrict__ w,
                float* __restrict__ out)
{
    __shared__ float zsh[8][DC];
    const int lane = threadIdx.x & 31, wwid = threadIdx.x >> 5;
    const int wglob = blockIdx.x * 8 + wwid;
    const int nwarp = gridDim.x * 8;
    const int n = g_cnt;

    for (int i = wglob; i < n; i += nwarp) {
        int qid = g_list[i];
        int b = qid >> 12, t = qid & 4095;
        const float* zc = z + (size_t)b * DC * TC + t;
        for (int d = lane; d < DC; d += 32) zsh[wwid][d] = zc[(size_t)d * TC];
        __syncwarp();
        float zq = 0.f;
        for (int d = 0; d < DC; ++d)
            zq = __fadd_rn(zq, __fmul_rn(zsh[wwid][d], zsh[wwid][d]));

        unsigned long long best = ~0ull;
        for (int j0 = 0; j0 < 16; j0 += 4) {
            float acc[4] = {0.f, 0.f, 0.f, 0.f};
            const float* w0 = w + (size_t)(lane + 32 * (j0 + 0)) * DC;
            const float* w1p = w + (size_t)(lane + 32 * (j0 + 1)) * DC;
            const float* w2p = w + (size_t)(lane + 32 * (j0 + 2)) * DC;
            const float* w3p = w + (size_t)(lane + 32 * (j0 + 3)) * DC;
            for (int d = 0; d < DC; ++d) {
                float zv = zsh[wwid][d];
                acc[0] = __fmaf_rn(zv, w0[d], acc[0]);
                acc[1] = __fmaf_rn(zv, w1p[d], acc[1]);
                acc[2] = __fmaf_rn(zv, w2p[d], acc[2]);
                acc[3] = __fmaf_rn(zv, w3p[d], acc[3]);
            }
            #pragma unroll
            for (int u = 0; u < 4; ++u) {
                int k = lane + 32 * (j0 + u);
                float c2 = __fmul_rn(2.0f, acc[u]);
                float t2v = __fsub_rn(zq, c2);
                float s  = __fadd_rn(t2v, g_wq[k]);
                unsigned long long cand =
                    (((unsigned long long)__float_as_uint(s)) << 32) | (uint32_t)k;
                if (cand < best) best = cand;
            }
        }
        #pragma unroll
        for (int off = 16; off; off >>= 1) {
            unsigned long long o = __shfl_xor_sync(0xffffffffu, best, off);
            if (o < best) best = o;
        }
        if (lane == 0) out[qid] = (float)(unsigned int)(best & 0xFFFFFFFFull);
        __syncwarp();
    }
}

extern "C" void kernel_launch(void* const* d_in, const int* in_sizes, int n_in,
                              void* d_out, int out_size)
{
    const float* z = (const float*)d_in[0];
    const float* w = (const float*)d_in[1];
    if (n_in >= 2 && in_sizes[0] == KC * DC && in_sizes[1] == BC * DC * TC) {
        z = (const float*)d_in[1];
        w = (const float*)d_in[0];
    }
    float* out = (float*)d_out;
    (void)out_size;

    cudaFuncSetAttribute(vq_dp4a_kernel,
                         cudaFuncAttributeMaxDynamicSharedMemorySize, SMEM_BYTES);

    prep_kernel<<<KC, DC>>>(w);
    dim3 grid(TC / BT, BC);   // (32, 32)
    vq_dp4a_kernel<<<grid, 256, SMEM_BYTES>>>(z, out);
    fix_kernel<<<128, 256>>>(z, w, out);
}